// round 15
// baseline (speedup 1.0000x reference)
#include <cuda_runtime.h>
#include <cuda_bf16.h>

// Sparsemax rows of 2048 fp32 — persistent CTA, TWO rows per iteration.
// 512 threads: each thread owns one float4 of row A and one of row B.
// Warp 0 solves row A while warp 1 solves row B (parallel solves), so the
// barrier + solve overhead is amortized over 2 rows (1 barrier per row).
// Algorithm per row (proven): static THETA gather via max-prefiltered shared
// atomics; Michelot on candidates; tau >= THETA self-certifies exactness
// (KKT: all discarded <= THETA <= tau); streaming float4 store; full-block
// Michelot fallback for general correctness.

#define ROWLEN  2048
#define THREADS 512
#define NWARP   (THREADS / 32)       // 16
#define F4PROW  (ROWLEN / 4)         // 512 == THREADS
#define CAP     64
#define THETA   2.25f
#define NEG_INF (-3.0e38f)
#define FULLM   0xffffffffu
#define OCC     3
#define GRID_CTAS (148 * OCC)

// Block-wide Michelot over one register float4 per thread (uniform entry only).
__device__ __forceinline__ float block_michelot(
    float4 q, float* s_red, float* s_cnt, float* s_btau, int lane, int wid, int tid)
{
    float tau;
    {
        float s = (q.x + q.y) + (q.z + q.w);
        #pragma unroll
        for (int o = 16; o > 0; o >>= 1) s += __shfl_xor_sync(FULLM, s, o);
        if (lane == 0) s_red[wid] = s;
        __syncthreads();
        if (tid == 0) {
            float tot = 0.0f;
            #pragma unroll
            for (int w = 0; w < NWARP; w++) tot += s_red[w];
            *s_btau = (tot - 1.0f) * (1.0f / (float)ROWLEN);
        }
        __syncthreads();
        tau = *s_btau;
    }
    int k_prev = ROWLEN;
    #pragma unroll 1
    for (int it = 0; it < 64; it++) {
        float s = 0.0f, cf = 0.0f;
        if (q.x > tau) { s += q.x; cf += 1.0f; }
        if (q.y > tau) { s += q.y; cf += 1.0f; }
        if (q.z > tau) { s += q.z; cf += 1.0f; }
        if (q.w > tau) { s += q.w; cf += 1.0f; }
        #pragma unroll
        for (int o = 16; o > 0; o >>= 1) {
            s  += __shfl_xor_sync(FULLM, s, o);
            cf += __shfl_xor_sync(FULLM, cf, o);
        }
        if (lane == 0) { s_red[wid] = s; s_cnt[wid] = cf; }
        __syncthreads();
        if (tid == 0) {
            float ts = 0.0f, tc = 0.0f;
            #pragma unroll
            for (int w = 0; w < NWARP; w++) { ts += s_red[w]; tc += s_cnt[w]; }
            *s_btau = (ts - 1.0f) / tc;
            s_cnt[0] = tc;
        }
        __syncthreads();
        tau = *s_btau;
        int k = (int)s_cnt[0];
        __syncthreads();
        if (k == k_prev) break;
        k_prev = k;
    }
    return tau;
}

__global__ __launch_bounds__(THREADS, OCC)
void sparsemax_kernel(const float* __restrict__ z, float* __restrict__ out, int rows) {
    const float4* __restrict__ z4   = reinterpret_cast<const float4*>(z);
    float4* __restrict__       out4 = reinterpret_cast<float4*>(out);
    const int tid  = threadIdx.x;
    const int lane = tid & 31;
    const int wid  = tid >> 5;
    const long long stride = gridDim.x;
    const long long npairs = ((long long)rows + 1) >> 1;

    __shared__ float s_cand[2][CAP];
    __shared__ int   s_n[2];
    __shared__ float s_tau[2];
    __shared__ int   s_ok[2];
    __shared__ float s_red[NWARP];
    __shared__ float s_cnt[NWARP];
    __shared__ float s_btau;

    long long p = blockIdx.x;
    if (p >= npairs) return;

    if (tid == 0) { s_n[0] = 0; s_n[1] = 0; }

    // prime: rows 2p and 2p+1 (one float4 each per thread)
    long long rA = 2 * p;
    bool hb = (rA + 1) < rows;
    float4 ca = __ldcs(&z4[rA * F4PROW + tid]);
    float4 cb = hb ? __ldcs(&z4[(rA + 1) * F4PROW + tid]) : make_float4(0.f, 0.f, 0.f, 0.f);
    __syncthreads();   // s_n init visible

    #pragma unroll 1
    while (true) {
        const long long pn = p + stride;
        const bool have_next = (pn < npairs);

        // ---- gather candidates for both rows (prefiltered atomics) ----
        {
            float m = fmaxf(fmaxf(ca.x, ca.y), fmaxf(ca.z, ca.w));
            if (m > THETA) {
                if (ca.x > THETA) { int ix = atomicAdd(&s_n[0], 1); if (ix < CAP) s_cand[0][ix] = ca.x; }
                if (ca.y > THETA) { int ix = atomicAdd(&s_n[0], 1); if (ix < CAP) s_cand[0][ix] = ca.y; }
                if (ca.z > THETA) { int ix = atomicAdd(&s_n[0], 1); if (ix < CAP) s_cand[0][ix] = ca.z; }
                if (ca.w > THETA) { int ix = atomicAdd(&s_n[0], 1); if (ix < CAP) s_cand[0][ix] = ca.w; }
            }
        }
        if (hb) {
            float m = fmaxf(fmaxf(cb.x, cb.y), fmaxf(cb.z, cb.w));
            if (m > THETA) {
                if (cb.x > THETA) { int ix = atomicAdd(&s_n[1], 1); if (ix < CAP) s_cand[1][ix] = cb.x; }
                if (cb.y > THETA) { int ix = atomicAdd(&s_n[1], 1); if (ix < CAP) s_cand[1][ix] = cb.y; }
                if (cb.z > THETA) { int ix = atomicAdd(&s_n[1], 1); if (ix < CAP) s_cand[1][ix] = cb.z; }
                if (cb.w > THETA) { int ix = atomicAdd(&s_n[1], 1); if (ix < CAP) s_cand[1][ix] = cb.w; }
            }
        }

        // ---- prefetch next pair (2 independent LDG.128 per thread) ----
        float4 pa, pb;
        bool hbn = false;
        if (have_next) {
            long long rAn = 2 * pn;
            pa  = __ldcs(&z4[rAn * F4PROW + tid]);
            hbn = (rAn + 1) < rows;
            if (hbn) pb = __ldcs(&z4[(rAn + 1) * F4PROW + tid]);
        }
        __syncthreads();   // both gathers complete

        // ---- parallel solves: warp 0 -> row A, warp 1 -> row B ----
        if (wid < 2) {
            const int sel = wid;
            const bool active = (sel == 0) || hb;
            if (active) {
                const int n = s_n[sel];
                float c0 = (lane < n)      ? s_cand[sel][lane]      : NEG_INF;
                float c1 = (lane + 32 < n) ? s_cand[sel][lane + 32] : NEG_INF;
                float s0 = (c0 > NEG_INF ? c0 : 0.0f) + (c1 > NEG_INF ? c1 : 0.0f);
                #pragma unroll
                for (int o = 16; o > 0; o >>= 1) s0 += __shfl_xor_sync(FULLM, s0, o);
                float tau = (s0 - 1.0f) / (float)(n > 0 ? (n <= CAP ? n : CAP) : 1);
                int prev = -1;
                #pragma unroll 1
                for (int it = 0; it < 32; it++) {
                    float s = 0.0f, cnt = 0.0f;
                    bool a0 = c0 > tau, a1 = c1 > tau;
                    s += a0 ? c0 : 0.0f;  cnt += a0 ? 1.0f : 0.0f;
                    s += a1 ? c1 : 0.0f;  cnt += a1 ? 1.0f : 0.0f;
                    #pragma unroll
                    for (int o = 16; o > 0; o >>= 1) {
                        s   += __shfl_xor_sync(FULLM, s, o);
                        cnt += __shfl_xor_sync(FULLM, cnt, o);
                    }
                    if (cnt == 0.0f) break;
                    tau = (s - 1.0f) / cnt;
                    int k = (int)cnt;
                    if (k == prev) break;
                    prev = k;
                }
                if (lane == 0) {
                    s_tau[sel] = tau;
                    s_ok[sel]  = (n > 0 && n <= CAP && tau >= THETA) ? 1 : 0;
                    s_n[sel]   = 0;
                }
            } else if (lane == 0) {
                s_ok[sel] = 1;   // row B absent: nothing to store, mark ok
                s_n[sel]  = 0;
            }
        }
        __syncthreads();   // taus visible, counters reset

        // ---- store row A ----
        {
            float tauA = s_ok[0] ? s_tau[0]
                                 : block_michelot(ca, s_red, s_cnt, &s_btau, lane, wid, tid);
            float4 o;
            o.x = fmaxf(ca.x - tauA, 0.0f);
            o.y = fmaxf(ca.y - tauA, 0.0f);
            o.z = fmaxf(ca.z - tauA, 0.0f);
            o.w = fmaxf(ca.w - tauA, 0.0f);
            __stcs(&out4[rA * F4PROW + tid], o);
        }
        // ---- store row B ----
        if (hb) {
            float tauB = s_ok[1] ? s_tau[1]
                                 : block_michelot(cb, s_red, s_cnt, &s_btau, lane, wid, tid);
            float4 o;
            o.x = fmaxf(cb.x - tauB, 0.0f);
            o.y = fmaxf(cb.y - tauB, 0.0f);
            o.z = fmaxf(cb.z - tauB, 0.0f);
            o.w = fmaxf(cb.w - tauB, 0.0f);
            __stcs(&out4[(rA + 1) * F4PROW + tid], o);
        }

        if (!have_next) break;
        p  = pn;
        rA = 2 * p;
        hb = hbn;
        ca = pa;
        cb = pb;
    }
}

extern "C" void kernel_launch(void* const* d_in, const int* in_sizes, int n_in,
                              void* d_out, int out_size) {
    const float* z = (const float*)d_in[0];
    float* out = (float*)d_out;
    int rows = in_sizes[0] / ROWLEN;
    long long npairs = ((long long)rows + 1) >> 1;
    int grid = GRID_CTAS < npairs ? GRID_CTAS : (int)npairs;
    sparsemax_kernel<<<grid, THREADS>>>(z, out, rows);
}

// round 16
// speedup vs baseline: 1.1490x; 1.1490x over previous
#include <cuda_runtime.h>
#include <cuda_bf16.h>

// Sparsemax rows of 2048 fp32 — persistent CTA-per-row with register prefetch
// (the proven 168.7us structure), with the solve window trimmed:
//  - THETA raised to 2.5: ~13 candidates/row (was ~25) -> half the serialized
//    shared atomics and faster Michelot convergence. Still safe: sum(z-2.5)+
//    ~4.1 >> 1 so tau* > THETA w.h.p., and tau >= THETA self-certifies
//    exactness via KKT (all discarded elements <= THETA <= tau). Fail-closed
//    fallback otherwise.
//  - single-register solve fast path for n <= 32 (probability ~99.9%).
// Full-block Michelot fallback over register-resident row keeps correctness.

#define ROWLEN  2048
#define THREADS 256
#define VPT     (ROWLEN / THREADS)   // 8
#define NWARP   (THREADS / 32)       // 8
#define F4PROW  (ROWLEN / 4)         // 512
#define CAP     64
#define THETA   2.5f
#define NEG_INF (-3.0e38f)
#define FULLM   0xffffffffu
#define OCC     6
#define GRID_CTAS (148 * OCC)

__global__ __launch_bounds__(THREADS, OCC)
void sparsemax_kernel(const float* __restrict__ z, float* __restrict__ out, int rows) {
    const float4* __restrict__ z4   = reinterpret_cast<const float4*>(z);
    float4* __restrict__       out4 = reinterpret_cast<float4*>(out);
    const int tid  = threadIdx.x;
    const int lane = tid & 31;
    const int wid  = tid >> 5;
    const long long stride = gridDim.x;

    __shared__ float s_cand[CAP];
    __shared__ int   s_n;
    __shared__ float s_tau;
    __shared__ int   s_ok;
    __shared__ float s_red[NWARP];
    __shared__ float s_cnt[NWARP];

    long long r = blockIdx.x;
    if (r >= rows) return;

    if (tid == 0) s_n = 0;

    // prime the pipeline: loads for the first row
    float4 a = __ldcs(&z4[r * F4PROW + tid]);
    float4 b = __ldcs(&z4[r * F4PROW + THREADS + tid]);
    __syncthreads();   // s_n init visible

    #pragma unroll 1
    while (true) {
        const long long rn = r + stride;
        float v[VPT] = {a.x, a.y, a.z, a.w, b.x, b.y, b.z, b.w};

        // ---- gather candidates > THETA (max-tree prefilter, rare atomics) ----
        float m = fmaxf(fmaxf(fmaxf(v[0], v[1]), fmaxf(v[2], v[3])),
                        fmaxf(fmaxf(v[4], v[5]), fmaxf(v[6], v[7])));
        if (m > THETA) {
            #pragma unroll
            for (int i = 0; i < VPT; i++) {
                if (v[i] > THETA) {
                    int idx = atomicAdd(&s_n, 1);
                    if (idx < CAP) s_cand[idx] = v[i];
                }
            }
        }

        // ---- prefetch next row BEFORE barriers/solve (hides DRAM latency) ----
        if (rn < rows) {
            a = __ldcs(&z4[rn * F4PROW + tid]);
            b = __ldcs(&z4[rn * F4PROW + THREADS + tid]);
        }
        __syncthreads();   // gather complete

        // ---- warp 0: Michelot on candidate set; certify tau >= THETA ----
        if (wid == 0) {
            const int n = s_n;
            float tau;
            if (n <= 32) {
                // fast path: one candidate register per lane (~99.9% of rows)
                float c0 = (lane < n) ? s_cand[lane] : NEG_INF;
                float s0 = (c0 > NEG_INF ? c0 : 0.0f);
                #pragma unroll
                for (int o = 16; o > 0; o >>= 1) s0 += __shfl_xor_sync(FULLM, s0, o);
                tau = (s0 - 1.0f) / (float)(n > 0 ? n : 1);
                int prev = -1;
                #pragma unroll 1
                for (int it = 0; it < 32; it++) {
                    float s = 0.0f, cnt = 0.0f;
                    bool a0 = c0 > tau;
                    s   += a0 ? c0 : 0.0f;
                    cnt += a0 ? 1.0f : 0.0f;
                    #pragma unroll
                    for (int o = 16; o > 0; o >>= 1) {
                        s   += __shfl_xor_sync(FULLM, s, o);
                        cnt += __shfl_xor_sync(FULLM, cnt, o);
                    }
                    if (cnt == 0.0f) break;
                    tau = (s - 1.0f) / cnt;
                    int k = (int)cnt;
                    if (k == prev) break;
                    prev = k;
                }
            } else {
                // two candidate registers per lane (n in (32, 64])
                float c0 = (lane < n)      ? s_cand[lane]      : NEG_INF;
                float c1 = (lane + 32 < n) ? s_cand[lane + 32] : NEG_INF;
                float s0 = (c0 > NEG_INF ? c0 : 0.0f) + (c1 > NEG_INF ? c1 : 0.0f);
                #pragma unroll
                for (int o = 16; o > 0; o >>= 1) s0 += __shfl_xor_sync(FULLM, s0, o);
                tau = (s0 - 1.0f) / (float)(n <= CAP ? n : CAP);
                int prev = -1;
                #pragma unroll 1
                for (int it = 0; it < 32; it++) {
                    float s = 0.0f, cnt = 0.0f;
                    bool a0 = c0 > tau, a1 = c1 > tau;
                    s += a0 ? c0 : 0.0f;  cnt += a0 ? 1.0f : 0.0f;
                    s += a1 ? c1 : 0.0f;  cnt += a1 ? 1.0f : 0.0f;
                    #pragma unroll
                    for (int o = 16; o > 0; o >>= 1) {
                        s   += __shfl_xor_sync(FULLM, s, o);
                        cnt += __shfl_xor_sync(FULLM, cnt, o);
                    }
                    if (cnt == 0.0f) break;
                    tau = (s - 1.0f) / cnt;
                    int k = (int)cnt;
                    if (k == prev) break;
                    prev = k;
                }
            }
            if (lane == 0) {
                s_tau = tau;
                s_ok  = (n > 0 && n <= CAP && tau >= THETA) ? 1 : 0;
                s_n   = 0;   // next gather begins only after the next barrier
            }
        }
        __syncthreads();   // s_tau/s_ok visible, s_n reset

        if (s_ok) {
            // ---- fast path: coalesced streaming projection store ----
            const float tau = s_tau;
            float4 o0, o1;
            o0.x = fmaxf(v[0] - tau, 0.0f);
            o0.y = fmaxf(v[1] - tau, 0.0f);
            o0.z = fmaxf(v[2] - tau, 0.0f);
            o0.w = fmaxf(v[3] - tau, 0.0f);
            o1.x = fmaxf(v[4] - tau, 0.0f);
            o1.y = fmaxf(v[5] - tau, 0.0f);
            o1.z = fmaxf(v[6] - tau, 0.0f);
            o1.w = fmaxf(v[7] - tau, 0.0f);
            __stcs(&out4[r * F4PROW + tid],           o0);
            __stcs(&out4[r * F4PROW + THREADS + tid], o1);
        } else {
            // ---- fallback: full-block Michelot over register-resident row ----
            float tau;
            {
                float s = 0.0f;
                #pragma unroll
                for (int i = 0; i < VPT; i++) s += v[i];
                #pragma unroll
                for (int o = 16; o > 0; o >>= 1) s += __shfl_xor_sync(FULLM, s, o);
                if (lane == 0) s_red[wid] = s;
                __syncthreads();
                if (tid == 0) {
                    float tot = 0.0f;
                    #pragma unroll
                    for (int w = 0; w < NWARP; w++) tot += s_red[w];
                    s_tau = (tot - 1.0f) * (1.0f / (float)ROWLEN);
                }
                __syncthreads();
                tau = s_tau;
            }
            int k_prev = ROWLEN;
            #pragma unroll 1
            for (int it = 0; it < 64; it++) {
                float s = 0.0f, cf = 0.0f;
                #pragma unroll
                for (int i = 0; i < VPT; i++) {
                    bool act = v[i] > tau;
                    s  += act ? v[i] : 0.0f;
                    cf += act ? 1.0f : 0.0f;
                }
                #pragma unroll
                for (int o = 16; o > 0; o >>= 1) {
                    s  += __shfl_xor_sync(FULLM, s, o);
                    cf += __shfl_xor_sync(FULLM, cf, o);
                }
                if (lane == 0) { s_red[wid] = s; s_cnt[wid] = cf; }
                __syncthreads();
                if (tid == 0) {
                    float ts = 0.0f, tc = 0.0f;
                    #pragma unroll
                    for (int w = 0; w < NWARP; w++) { ts += s_red[w]; tc += s_cnt[w]; }
                    s_tau = (ts - 1.0f) / tc;
                    s_cnt[0] = tc;
                }
                __syncthreads();
                tau = s_tau;
                int k = (int)s_cnt[0];
                __syncthreads();
                if (k == k_prev) break;
                k_prev = k;
            }
            float4 o0, o1;
            o0.x = fmaxf(v[0] - tau, 0.0f);
            o0.y = fmaxf(v[1] - tau, 0.0f);
            o0.z = fmaxf(v[2] - tau, 0.0f);
            o0.w = fmaxf(v[3] - tau, 0.0f);
            o1.x = fmaxf(v[4] - tau, 0.0f);
            o1.y = fmaxf(v[5] - tau, 0.0f);
            o1.z = fmaxf(v[6] - tau, 0.0f);
            o1.w = fmaxf(v[7] - tau, 0.0f);
            out4[r * F4PROW + tid]           = o0;
            out4[r * F4PROW + THREADS + tid] = o1;
        }

        if (rn >= rows) break;
        r = rn;
    }
}

extern "C" void kernel_launch(void* const* d_in, const int* in_sizes, int n_in,
                              void* d_out, int out_size) {
    const float* z = (const float*)d_in[0];
    float* out = (float*)d_out;
    int rows = in_sizes[0] / ROWLEN;
    int grid = GRID_CTAS < rows ? GRID_CTAS : rows;
    sparsemax_kernel<<<grid, THREADS>>>(z, out, rows);
}